// round 16
// baseline (speedup 1.0000x reference)
#include <cuda_runtime.h>
#include <cstdint>

// Problem constants
#define QQ 30
#define KK 1024
#define DD 128
#define BB 16
#define TT 2048
#define NTOK (BB*TT)          // 32768 tokens
#define OUT_ELEMS (NTOK*DD)   // 4194304 quantized elements

// Tiling
#define TM 128                // tokens per CTA
#define KC 64                 // codes per chunk (double-buffered)
#define NCH 16                // chunks per stage
#define NT 256                // threads per CTA
#define KPW8 36               // padded int8 row: 32 data words + 4 pad
#define CHB8 (KC*KPW8*4)      // 9216 bytes per chunk buffer
#define CAP 4096              // candidate list capacity (per CTA, in gmem)
#define NBLK (NTOK/TM)        // 256 CTAs

// Scratch (no cudaMalloc): code norms, int8 codebook (stride-36 rows), per-q
// max c2 + max |c|, per-CTA candidate lists.
__device__ float    g_cn[QQ*KK];
__device__ unsigned g_cmax[QQ];     // max c2 per stage (window)
__device__ unsigned g_camax[QQ];    // max |c| per stage (quant scale)
__device__ __align__(16) unsigned g_cb8[(size_t)QQ*KK*KPW8];   // 4.4 MB
__device__ unsigned long long g_cand[(size_t)NBLK*CAP];        // 8 MB

// SMEM layout (bytes): total 105,600 -> 2 CTAs/SM
#define SM_BEST 0          // 128 u64
#define SM_RED  1024       // 8 doubles
#define SM_R2   1088       // 128 f
#define SM_SMIN 1600       // 128 f
#define SM_SR   2112       // 128 f (per-token quant scale)
#define SM_C2   2624       // 2*64 f (double-buffered)
#define SM_CNT  3136       // int (+pad)
#define SM_RS   3200       // 128*128 f = 65536
#define SM_RS8  68736      // 128*36*4 = 18432 (int8 residual rows)
#define SM_CS   87168      // 2 * 9216 = 18432 (int8 code chunks)
#define SM_TOTAL 105600

// ---------------------------------------------------------------------------
// Reference-exact square-sum reduce (validated bit-exact -- DO NOT TOUCH)
// ---------------------------------------------------------------------------
#define RED_ACC(a0, a1, v0, v1, v2, v3, v4, v5, v6, v7)                  \
    do {                                                                 \
        a0[0] = __fmaf_rn((v0), (v0), a0[0]);                            \
        a0[1] = __fmaf_rn((v1), (v1), a0[1]);                            \
        a0[2] = __fmaf_rn((v2), (v2), a0[2]);                            \
        a0[3] = __fmaf_rn((v3), (v3), a0[3]);                            \
        a1[0] = __fmaf_rn((v4), (v4), a1[0]);                            \
        a1[1] = __fmaf_rn((v5), (v5), a1[1]);                            \
        a1[2] = __fmaf_rn((v6), (v6), a1[2]);                            \
        a1[3] = __fmaf_rn((v7), (v7), a1[3]);                            \
    } while (0)

static __device__ __forceinline__ float red_combine(const float a0[4], const float a1[4])
{
    float v0 = __fadd_rn(a0[0], a1[0]);
    float v1 = __fadd_rn(a0[1], a1[1]);
    float v2 = __fadd_rn(a0[2], a1[2]);
    float v3 = __fadd_rn(a0[3], a1[3]);
    return __fadd_rn(__fadd_rn(__fadd_rn(v0, v1), v2), v3);
}

static __device__ __forceinline__ unsigned smem_u32(const void* p)
{
    unsigned a;
    asm("{ .reg .u64 t; cvta.to.shared.u64 t, %1; cvt.u32.u64 %0, t; }"
        : "=r"(a) : "l"(p));
    return a;
}

static __device__ __forceinline__ void imma_s8(int& c0, int& c1, int& c2, int& c3,
                                               unsigned a0, unsigned a1, unsigned a2, unsigned a3,
                                               unsigned b0, unsigned b1)
{
    asm("mma.sync.aligned.m16n8k32.row.col.s32.s8.s8.s32 "
        "{%0,%1,%2,%3}, {%4,%5,%6,%7}, {%8,%9}, {%0,%1,%2,%3};"
        : "+r"(c0), "+r"(c1), "+r"(c2), "+r"(c3)
        : "r"(a0), "r"(a1), "r"(a2), "r"(a3), "r"(b0), "r"(b1));
}

#define CP_ASYNC16(dst, src) \
    asm volatile("cp.async.cg.shared.global [%0], [%1], 16;" \
                 :: "r"(dst), "l"(src) : "memory")
#define CP_COMMIT() asm volatile("cp.async.commit_group;" ::: "memory")
#define CP_WAIT1()  asm volatile("cp.async.wait_group 1;" ::: "memory")
#define CP_WAIT0()  asm volatile("cp.async.wait_group 0;" ::: "memory")

static __device__ __forceinline__ unsigned pack4(int q0, int q1, int q2, int q3)
{
    return (unsigned)(q0 & 0xFF) | ((unsigned)(q1 & 0xFF) << 8)
         | ((unsigned)(q2 & 0xFF) << 16) | ((unsigned)(q3 & 0xFF) << 24);
}

// Quantize token row from rs (own writes, same thread) into rs8 + sr.
static __device__ __forceinline__ void quant_row(const float* rs, unsigned* rs8w,
                                                 float* sr_s, int tok, float rmax)
{
    float inv = (rmax > 0.f) ? (127.0f / rmax) : 0.f;
    sr_s[tok] = rmax * (1.0f / 127.0f);
    #pragma unroll
    for (int w = 0; w < 32; w++) {
        int d = w * 4;
        int q0 = __float2int_rn(rs[(d+0)*TM + tok] * inv);
        int q1 = __float2int_rn(rs[(d+1)*TM + tok] * inv);
        int q2 = __float2int_rn(rs[(d+2)*TM + tok] * inv);
        int q3 = __float2int_rn(rs[(d+3)*TM + tok] * inv);
        rs8w[tok * KPW8 + w] = pack4(q0, q1, q2, q3);
    }
}

// Validated exact score key for (tok,k): chain ascending d, strict combine.
static __device__ __forceinline__ unsigned long long exact_key(
    const float* rs, const float* cb, const float* cn, float r2v,
    int q, int tok, int k)
{
    const float4* crow = (const float4*)(cb + ((size_t)q * KK + k) * DD);
    float acc = 0.0f;
    #pragma unroll 8
    for (int j = 0; j < DD/4; j++) {
        float4 c4 = __ldg(crow + j);
        int d = j * 4;
        acc = __fmaf_rn(rs[(d+0)*TM + tok], c4.x, acc);
        acc = __fmaf_rn(rs[(d+1)*TM + tok], c4.y, acc);
        acc = __fmaf_rn(rs[(d+2)*TM + tok], c4.z, acc);
        acc = __fmaf_rn(rs[(d+3)*TM + tok], c4.w, acc);
    }
    float e2 = __fmul_rn(2.0f, acc);
    float u  = __fsub_rn(r2v, e2);
    float s  = __fadd_rn(u, cn[k]);
    unsigned uu = __float_as_uint(s);
    uu = (uu & 0x80000000u) ? ~uu : (uu | 0x80000000u);
    return ((unsigned long long)uu << 32) | (unsigned)k;
}

// ---------------------------------------------------------------------------
// Prep 0: zero loss slot + per-q accumulators.
// ---------------------------------------------------------------------------
__global__ void rvq_prep0_kernel(float* __restrict__ out, int write_loss)
{
    if (write_loss && threadIdx.x == 0) out[OUT_ELEMS] = 0.0f;
    if (threadIdx.x < QQ) { g_cmax[threadIdx.x] = 0u; g_camax[threadIdx.x] = 0u; }
}

// ---------------------------------------------------------------------------
// Prep B1: c2 (validated chain) + per-q max c2 + per-q max |c|.
// ---------------------------------------------------------------------------
__global__ void rvq_norm_kernel(const float* __restrict__ cb)
{
    int gw = blockIdx.x * blockDim.x + threadIdx.x;   // code row (q*KK+k)
    if (gw >= QQ * KK) return;
    const float4* row = ((const float4*)cb) + (size_t)gw * (DD/4);
    float a0[4] = {0.f,0.f,0.f,0.f}, a1[4] = {0.f,0.f,0.f,0.f};
    float amax = 0.f;
    #pragma unroll
    for (int j = 0; j < 16; j++) {
        float4 A = __ldg(row + 2*j);
        float4 B = __ldg(row + 2*j + 1);
        RED_ACC(a0, a1, A.x, A.y, A.z, A.w, B.x, B.y, B.z, B.w);
        amax = fmaxf(amax, fmaxf(fmaxf(fabsf(A.x), fabsf(A.y)),
                                 fmaxf(fabsf(A.z), fabsf(A.w))));
        amax = fmaxf(amax, fmaxf(fmaxf(fabsf(B.x), fabsf(B.y)),
                                 fmaxf(fabsf(B.z), fabsf(B.w))));
    }
    float c2 = red_combine(a0, a1);
    g_cn[gw] = c2;
    atomicMax(&g_cmax[gw >> 10],  __float_as_uint(c2));
    atomicMax(&g_camax[gw >> 10], __float_as_uint(amax));
}

// ---------------------------------------------------------------------------
// Prep B2: int8-quantized codebook rows, stride-36 words.
// ---------------------------------------------------------------------------
__global__ void rvq_quant_kernel(const float* __restrict__ cb)
{
    int gw = blockIdx.x * blockDim.x + threadIdx.x;
    if (gw >= QQ * KK) return;
    float camax = __uint_as_float(g_camax[gw >> 10]);
    float inv = (camax > 0.f) ? (127.f / camax) : 0.f;
    const float4* row = ((const float4*)cb) + (size_t)gw * (DD/4);
    unsigned* dst = g_cb8 + (size_t)gw * KPW8;
    #pragma unroll
    for (int j = 0; j < 32; j++) {
        float4 v = __ldg(row + j);
        dst[j] = pack4(__float2int_rn(v.x * inv), __float2int_rn(v.y * inv),
                       __float2int_rn(v.z * inv), __float2int_rn(v.w * inv));
    }
    dst[32] = dst[33] = dst[34] = dst[35] = 0u;
}

// ---------------------------------------------------------------------------
// Main kernel: int8 IMMA filter (4 mma/group, cp.async double-buffered B,
// 2 CTAs/SM) + validated exact rescore / update / r2 / loss.
// ---------------------------------------------------------------------------
__global__ __launch_bounds__(NT, 2)
void rvq_kernel(const float* __restrict__ x,
                const float* __restrict__ cb,
                float* __restrict__ out, int write_loss)
{
    extern __shared__ char sm[];
    unsigned long long* bestkey = (unsigned long long*)(sm + SM_BEST);
    double*   red  = (double*)(sm + SM_RED);
    float*    r2_s = (float*)(sm + SM_R2);
    float*    smin = (float*)(sm + SM_SMIN);
    float*    sr_s = (float*)(sm + SM_SR);
    float*    c2s  = (float*)(sm + SM_C2);
    int*      cnts = (int*)(sm + SM_CNT);
    float*    rs   = (float*)(sm + SM_RS);
    unsigned* rs8w = (unsigned*)(sm + SM_RS8);
    unsigned* cs_w = (unsigned*)(sm + SM_CS);
    float4*   rs4  = (float4*)rs;
    const unsigned csb = smem_u32(sm + SM_CS);
    const unsigned c2b = smem_u32(sm + SM_C2);

    const int tid  = threadIdx.x;
    const int lane = tid & 31;
    const int g    = lane >> 2;       // mma group id (0..7)
    const int tig  = lane & 3;        // thread in group
    const int tw   = (tid >> 5) * 16; // warp token base

    const int blk = blockIdx.x;
    const int b   = blk >> 4;
    const int t0  = (blk & 15) * TM;
    const float* xb = x + (size_t)b * DD * TT + t0;
    unsigned long long* candg = g_cand + (size_t)blk * CAP;

    // Load initial residual r0 = x (transposed [d][token])
    for (int i = tid; i < DD*TM/4; i += NT) {
        int tok4 = i & 31, d = i >> 5;
        float4 v = __ldg((const float4*)(xb + (size_t)d * TT) + tok4);
        rs4[d * (TM/4) + tok4] = v;
    }
    __syncthreads();

    // Initial r2 (validated association) + rmax + int8 quantize
    if (tid < TM) {
        float a0[4] = {0.f,0.f,0.f,0.f}, a1[4] = {0.f,0.f,0.f,0.f};
        float rmax = 0.f;
        #pragma unroll
        for (int j = 0; j < 16; j++) {
            int d = 8*j;
            float v0 = rs[(d+0)*TM + tid], v1 = rs[(d+1)*TM + tid];
            float v2 = rs[(d+2)*TM + tid], v3 = rs[(d+3)*TM + tid];
            float v4 = rs[(d+4)*TM + tid], v5 = rs[(d+5)*TM + tid];
            float v6 = rs[(d+6)*TM + tid], v7 = rs[(d+7)*TM + tid];
            RED_ACC(a0, a1, v0, v1, v2, v3, v4, v5, v6, v7);
            rmax = fmaxf(rmax, fmaxf(fmaxf(fabsf(v0), fabsf(v1)),
                                     fmaxf(fabsf(v2), fabsf(v3))));
            rmax = fmaxf(rmax, fmaxf(fmaxf(fabsf(v4), fabsf(v5)),
                                     fmaxf(fabsf(v6), fabsf(v7))));
        }
        r2_s[tid] = red_combine(a0, a1);
        quant_row(rs, rs8w, sr_s, tid, rmax);
    }
    __syncthreads();

    double lossAcc = 0.0;

    for (int q = 0; q < QQ; q++) {
        if (tid < TM) bestkey[tid] = 0xFFFFFFFFFFFFFFFFull;
        if (tid == 0) cnts[0] = 0;

        const float* cnq = g_cn + q * KK;
        const float sc_q = __uint_as_float(g_camax[q]) * (1.0f / 127.0f);

        // A fragments: 16 LDS from the int8 residual image (conflict-free)
        const int tlo = tw + g, thi = tw + 8 + g;
        unsigned af[4][4];
        #pragma unroll
        for (int kt = 0; kt < 4; kt++) {
            af[kt][0] = rs8w[tlo*KPW8 + kt*8 + tig];
            af[kt][1] = rs8w[thi*KPW8 + kt*8 + tig];
            af[kt][2] = rs8w[tlo*KPW8 + kt*8 + 4 + tig];
            af[kt][3] = rs8w[thi*KPW8 + kt*8 + 4 + tig];
        }
        const float f_lo = 2.0f * sr_s[tlo] * sc_q;
        const float f_hi = 2.0f * sr_s[thi] * sc_q;

        const float cmax = __uint_as_float(g_cmax[q]);
        const float wlo = __fmaf_rn(0.07f, sqrtf(r2_s[tlo] * cmax), 2.0f);
        const float whi = __fmaf_rn(0.07f, sqrtf(r2_s[thi] * cmax), 2.0f);
        float mlo = 3.4e38f, mhi = 3.4e38f;

        // Prefetch chunk 0 into buffer 0 (async)
        {
            const char* src = (const char*)(g_cb8 + (size_t)(q*KK) * KPW8);
            for (int i = tid; i < CHB8/16; i += NT)
                CP_ASYNC16(csb + (unsigned)(i*16), src + i*16);
            if (tid < 16)
                CP_ASYNC16(c2b + (unsigned)(tid*16), (const char*)cnq + tid*16);
            CP_COMMIT();
        }

        for (int ch = 0; ch < NCH; ch++) {
            const int buf = ch & 1;
            __syncthreads();   // prev compute on buf^1 done before overwrite
            if (ch < NCH - 1) {
                const int nb = buf ^ 1;
                const char* src =
                    (const char*)(g_cb8 + (size_t)(q*KK + (ch+1)*KC) * KPW8);
                for (int i = tid; i < CHB8/16; i += NT)
                    CP_ASYNC16(csb + (unsigned)(nb*CHB8 + i*16), src + i*16);
                if (tid < 16)
                    CP_ASYNC16(c2b + (unsigned)(nb*256 + tid*16),
                               (const char*)(cnq + (ch+1)*KC) + tid*16);
                CP_COMMIT();
                CP_WAIT1();
            } else {
                CP_WAIT0();
            }
            __syncthreads();

            const unsigned* bw = cs_w + buf*(CHB8/4);
            #pragma unroll 2
            for (int nt = 0; nt < 8; nt++) {   // 8 groups per 64-code chunk
                // B fragments: 8 scalar LDS, conflict-free (stride 36 words)
                const unsigned* brow = bw + (nt*8 + g)*KPW8 + tig;
                int ic0 = 0, ic1 = 0, ic2 = 0, ic3 = 0;
                #pragma unroll
                for (int kt = 0; kt < 4; kt++) {
                    unsigned b0 = brow[kt*8];
                    unsigned b1 = brow[kt*8 + 4];
                    imma_s8(ic0, ic1, ic2, ic3,
                            af[kt][0], af[kt][1], af[kt][2], af[kt][3], b0, b1);
                }

                float cc0 = c2s[buf*KC + nt*8 + 2*tig];
                float cc1 = c2s[buf*KC + nt*8 + 2*tig + 1];
                float s0 = __fmaf_rn(-f_lo, (float)ic0, cc0);   // token tlo
                float s1 = __fmaf_rn(-f_lo, (float)ic1, cc1);
                float s2 = __fmaf_rn(-f_hi, (float)ic2, cc0);   // token thi
                float s3 = __fmaf_rn(-f_hi, (float)ic3, cc1);
                mlo = fminf(mlo, fminf(s0, s1));
                mhi = fminf(mhi, fminf(s2, s3));
                mlo = fminf(mlo, __shfl_xor_sync(0xffffffffu, mlo, 1));
                mlo = fminf(mlo, __shfl_xor_sync(0xffffffffu, mlo, 2));
                mhi = fminf(mhi, __shfl_xor_sync(0xffffffffu, mhi, 1));
                mhi = fminf(mhi, __shfl_xor_sync(0xffffffffu, mhi, 2));
                int code0 = ch*KC + nt*8 + 2*tig;
                float tl = mlo + wlo, th = mhi + whi;
                if (s0 <= tl || s1 <= tl || s2 <= th || s3 <= th) {
                    if (s0 <= tl) { int p = atomicAdd(cnts, 1); if (p < CAP)
                        candg[p] = ((unsigned long long)__float_as_uint(s0) << 32)
                                 | (unsigned)((tlo << 10) | code0); }
                    if (s1 <= tl) { int p = atomicAdd(cnts, 1); if (p < CAP)
                        candg[p] = ((unsigned long long)__float_as_uint(s1) << 32)
                                 | (unsigned)((tlo << 10) | (code0 + 1)); }
                    if (s2 <= th) { int p = atomicAdd(cnts, 1); if (p < CAP)
                        candg[p] = ((unsigned long long)__float_as_uint(s2) << 32)
                                 | (unsigned)((thi << 10) | code0); }
                    if (s3 <= th) { int p = atomicAdd(cnts, 1); if (p < CAP)
                        candg[p] = ((unsigned long long)__float_as_uint(s3) << 32)
                                 | (unsigned)((thi << 10) | (code0 + 1)); }
                }
            }
        }
        if (tig == 0) { smin[tlo] = mlo; smin[thi] = mhi; }
        __syncthreads();

        int cnt = cnts[0];
        if (cnt <= CAP) {
            // Exact rescore of survivors (validated chain)
            for (int i = tid; i < cnt; i += NT) {
                unsigned long long e = candg[i];
                float sv = __uint_as_float((unsigned)(e >> 32));
                unsigned tc = (unsigned)e;
                int tok = (tc >> 10) & 127, k = tc & 1023;
                float Wk = __fmaf_rn(0.07f, sqrtf(r2_s[tok] * cmax), 2.0f);
                if (sv <= smin[tok] + Wk) {
                    unsigned long long key =
                        exact_key(rs, cb, cnq, r2_s[tok], q, tok, k);
                    atomicMin(&bestkey[tok], key);
                }
            }
        } else {
            // overflow fallback: exact full scan (deterministic, ~never)
            if (tid < TM) {
                unsigned long long bk = 0xFFFFFFFFFFFFFFFFull;
                for (int k = 0; k < KK; k++) {
                    unsigned long long key =
                        exact_key(rs, cb, cnq, r2_s[tid], q, tid, k);
                    if (key < bk) bk = key;
                }
                bestkey[tid] = bk;
            }
        }
        __syncthreads();

        // Residual update + next r2 (validated path) + rmax + quantize
        if (tid < TM) {
            const int tok = tid;
            const int widx = (int)(bestkey[tok] & 0xFFFFFFFFull);
            const float4* crow =
                (const float4*)(cb + ((size_t)q * KK + widx) * DD);
            float a0[4] = {0.f,0.f,0.f,0.f}, a1[4] = {0.f,0.f,0.f,0.f};
            float lsum = 0.0f;
            float rmax = 0.f;
            #pragma unroll
            for (int j = 0; j < 16; j++) {
                float4 cA = __ldg(crow + 2*j);
                float4 cB = __ldg(crow + 2*j + 1);
                int d = 8*j;
                float n0 = __fsub_rn(rs[(d+0)*TM + tok], cA.x);
                float n1 = __fsub_rn(rs[(d+1)*TM + tok], cA.y);
                float n2 = __fsub_rn(rs[(d+2)*TM + tok], cA.z);
                float n3 = __fsub_rn(rs[(d+3)*TM + tok], cA.w);
                float n4 = __fsub_rn(rs[(d+4)*TM + tok], cB.x);
                float n5 = __fsub_rn(rs[(d+5)*TM + tok], cB.y);
                float n6 = __fsub_rn(rs[(d+6)*TM + tok], cB.z);
                float n7 = __fsub_rn(rs[(d+7)*TM + tok], cB.w);
                rs[(d+0)*TM + tok] = n0;
                rs[(d+1)*TM + tok] = n1;
                rs[(d+2)*TM + tok] = n2;
                rs[(d+3)*TM + tok] = n3;
                rs[(d+4)*TM + tok] = n4;
                rs[(d+5)*TM + tok] = n5;
                rs[(d+6)*TM + tok] = n6;
                rs[(d+7)*TM + tok] = n7;
                RED_ACC(a0, a1, n0, n1, n2, n3, n4, n5, n6, n7);
                lsum += n0*n0 + n1*n1 + n2*n2 + n3*n3
                      + n4*n4 + n5*n5 + n6*n6 + n7*n7;
                rmax = fmaxf(rmax, fmaxf(fmaxf(fabsf(n0), fabsf(n1)),
                                         fmaxf(fabsf(n2), fabsf(n3))));
                rmax = fmaxf(rmax, fmaxf(fmaxf(fabsf(n4), fabsf(n5)),
                                         fmaxf(fabsf(n6), fabsf(n7))));
            }
            r2_s[tok] = red_combine(a0, a1);
            lossAcc += (double)lsum;
            quant_row(rs, rs8w, sr_s, tok, rmax);
        }
        __syncthreads();   // rs/rs8/sr/r2 visible before next stage
    }

    // quantized = x - r_final (telescoped), layout [B,D,T]
    for (int i = tid; i < DD*TM/4; i += NT) {
        int tok4 = i & 31, d = i >> 5;
        float4 xv = __ldg((const float4*)(xb + (size_t)d * TT) + tok4);
        float4 rv = rs4[d * (TM/4) + tok4];
        float4 o;
        o.x = xv.x - rv.x; o.y = xv.y - rv.y;
        o.z = xv.z - rv.z; o.w = xv.w - rv.w;
        ((float4*)(out + ((size_t)b * DD + d) * TT + t0))[tok4] = o;
    }

    // total_loss = sum_q mean(r_{q+1}^2)
    if (write_loss) {
        #pragma unroll
        for (int off = 16; off > 0; off >>= 1)
            lossAcc += __shfl_xor_sync(0xffffffffu, lossAcc, off);
        if ((tid & 31) == 0) red[tid >> 5] = lossAcc;
        __syncthreads();
        if (tid == 0) {
            double s = 0.0;
            #pragma unroll
            for (int w = 0; w < 8; w++) s += red[w];
            atomicAdd(out + OUT_ELEMS, (float)(s * (1.0 / (double)OUT_ELEMS)));
        }
    }
}

// ---------------------------------------------------------------------------
extern "C" void kernel_launch(void* const* d_in, const int* in_sizes, int n_in,
                              void* d_out, int out_size)
{
    const float* x  = (const float*)d_in[0];   // [16,128,2048] fp32
    const float* cb = (const float*)d_in[1];   // [30,1024,128] fp32
    float* out = (float*)d_out;                // [16,128,2048] + loss scalar
    int write_loss = (out_size > OUT_ELEMS) ? 1 : 0;

    rvq_prep0_kernel<<<1, 64>>>(out, write_loss);
    rvq_norm_kernel<<<(QQ*KK + 255)/256, 256>>>(cb);
    rvq_quant_kernel<<<(QQ*KK + 255)/256, 256>>>(cb);

    cudaFuncSetAttribute(rvq_kernel,
                         cudaFuncAttributeMaxDynamicSharedMemorySize, SM_TOTAL);
    rvq_kernel<<<NBLK, NT, SM_TOTAL>>>(x, cb, out, write_loss);
}

// round 17
// speedup vs baseline: 1.4237x; 1.4237x over previous
#include <cuda_runtime.h>
#include <cstdint>

// Problem constants
#define QQ 30
#define KK 1024
#define DD 128
#define BB 16
#define TT 2048
#define NTOK (BB*TT)          // 32768 tokens
#define OUT_ELEMS (NTOK*DD)   // 4194304 quantized elements

// Tiling
#define TM 128                // tokens per CTA
#define KC 64                 // codes per chunk (double-buffered)
#define NCH 16                // chunks per stage
#define NT 256                // threads per CTA
#define KPW 68                // padded bf16 row: 64 data words + 4 pad
#define CHB (KC*KPW*4)        // 17408 bytes per chunk buffer
#define CAP 4096              // candidate list capacity (per CTA, in gmem)
#define NBLK (NTOK/TM)        // 256 CTAs

// Scratch (no cudaMalloc): code norms, bf16 codebook (padded rows), per-q max
// c2, per-CTA candidate lists.
__device__ float    g_cn[QQ*KK];
__device__ unsigned g_cb16[(size_t)QQ*KK*KPW];           // 8.36 MB
__device__ unsigned g_cmax[QQ];
__device__ unsigned long long g_cand[(size_t)NBLK*CAP];  // 8 MB

// SMEM layout (bytes): total 103,040 -> 2 CTAs/SM
#define SM_BEST 0          // 128 u64
#define SM_RED  1024       // 8 doubles
#define SM_R2   1088       // 128 f
#define SM_SMIN 1600       // 128 f
#define SM_C2   2112       // 2*64 f (double-buffered)
#define SM_CNT  2624       // int (+pad)
#define SM_RS   2688       // 128*128 f = 65536
#define SM_CS   68224      // 2 * 17408 = 34816
#define SM_TOTAL 103040

// ---------------------------------------------------------------------------
// Reference-exact square-sum reduce (validated bit-exact -- DO NOT TOUCH)
// ---------------------------------------------------------------------------
#define RED_ACC(a0, a1, v0, v1, v2, v3, v4, v5, v6, v7)                  \
    do {                                                                 \
        a0[0] = __fmaf_rn((v0), (v0), a0[0]);                            \
        a0[1] = __fmaf_rn((v1), (v1), a0[1]);                            \
        a0[2] = __fmaf_rn((v2), (v2), a0[2]);                            \
        a0[3] = __fmaf_rn((v3), (v3), a0[3]);                            \
        a1[0] = __fmaf_rn((v4), (v4), a1[0]);                            \
        a1[1] = __fmaf_rn((v5), (v5), a1[1]);                            \
        a1[2] = __fmaf_rn((v6), (v6), a1[2]);                            \
        a1[3] = __fmaf_rn((v7), (v7), a1[3]);                            \
    } while (0)

static __device__ __forceinline__ float red_combine(const float a0[4], const float a1[4])
{
    float v0 = __fadd_rn(a0[0], a1[0]);
    float v1 = __fadd_rn(a0[1], a1[1]);
    float v2 = __fadd_rn(a0[2], a1[2]);
    float v3 = __fadd_rn(a0[3], a1[3]);
    return __fadd_rn(__fadd_rn(__fadd_rn(v0, v1), v2), v3);
}

// bf16x2 pack: low half = lo, high half = hi
static __device__ __forceinline__ unsigned bf16pack(float lo, float hi)
{
    unsigned r;
    asm("cvt.rn.bf16x2.f32 %0, %1, %2;" : "=r"(r) : "f"(hi), "f"(lo));
    return r;
}

static __device__ __forceinline__ unsigned smem_u32(const void* p)
{
    unsigned a;
    asm("{ .reg .u64 t; cvta.to.shared.u64 t, %1; cvt.u32.u64 %0, t; }"
        : "=r"(a) : "l"(p));
    return a;
}

static __device__ __forceinline__ void mma_bf16(float& c0, float& c1, float& c2, float& c3,
                                                unsigned a0, unsigned a1, unsigned a2, unsigned a3,
                                                unsigned b0, unsigned b1)
{
    asm("mma.sync.aligned.m16n8k16.row.col.f32.bf16.bf16.f32 "
        "{%0,%1,%2,%3}, {%4,%5,%6,%7}, {%8,%9}, {%0,%1,%2,%3};"
        : "+f"(c0), "+f"(c1), "+f"(c2), "+f"(c3)
        : "r"(a0), "r"(a1), "r"(a2), "r"(a3), "r"(b0), "r"(b1));
}

static __device__ __forceinline__ void ldm4(unsigned* r, unsigned addr)
{
    asm volatile("ldmatrix.sync.aligned.m8n8.x4.shared.b16 {%0,%1,%2,%3}, [%4];"
                 : "=r"(r[0]), "=r"(r[1]), "=r"(r[2]), "=r"(r[3]) : "r"(addr));
}

#define CP_ASYNC16(dst, src) \
    asm volatile("cp.async.cg.shared.global [%0], [%1], 16;" \
                 :: "r"(dst), "l"(src) : "memory")
#define CP_COMMIT() asm volatile("cp.async.commit_group;" ::: "memory")
#define CP_WAIT1()  asm volatile("cp.async.wait_group 1;" ::: "memory")
#define CP_WAIT0()  asm volatile("cp.async.wait_group 0;" ::: "memory")

// Validated exact score key for (tok,k): chain ascending d, strict combine.
static __device__ __forceinline__ unsigned long long exact_key(
    const float* rs, const float* cb, const float* cn, float r2v,
    int q, int tok, int k)
{
    const float4* crow = (const float4*)(cb + ((size_t)q * KK + k) * DD);
    float acc = 0.0f;
    #pragma unroll 8
    for (int j = 0; j < DD/4; j++) {
        float4 c4 = __ldg(crow + j);
        int d = j * 4;
        acc = __fmaf_rn(rs[(d+0)*TM + tok], c4.x, acc);
        acc = __fmaf_rn(rs[(d+1)*TM + tok], c4.y, acc);
        acc = __fmaf_rn(rs[(d+2)*TM + tok], c4.z, acc);
        acc = __fmaf_rn(rs[(d+3)*TM + tok], c4.w, acc);
    }
    float e2 = __fmul_rn(2.0f, acc);
    float u  = __fsub_rn(r2v, e2);
    float s  = __fadd_rn(u, cn[k]);
    unsigned uu = __float_as_uint(s);
    uu = (uu & 0x80000000u) ? ~uu : (uu | 0x80000000u);
    return ((unsigned long long)uu << 32) | (unsigned)k;
}

// ---------------------------------------------------------------------------
// Prep 0: zero loss slot + cmax accumulators.
// ---------------------------------------------------------------------------
__global__ void rvq_prep0_kernel(float* __restrict__ out, int write_loss)
{
    if (write_loss && threadIdx.x == 0) out[OUT_ELEMS] = 0.0f;
    if (threadIdx.x < QQ) g_cmax[threadIdx.x] = 0u;
}

// ---------------------------------------------------------------------------
// Prep B: per code row: c2 (validated chain), bf16 packed row, cmax.
// ---------------------------------------------------------------------------
__global__ void rvq_norm_kernel(const float* __restrict__ cb)
{
    int gw = blockIdx.x * blockDim.x + threadIdx.x;   // code row (q*KK+k)
    if (gw >= QQ * KK) return;
    const float4* row = ((const float4*)cb) + (size_t)gw * (DD/4);
    unsigned* dst = g_cb16 + (size_t)gw * KPW;
    float a0[4] = {0.f,0.f,0.f,0.f}, a1[4] = {0.f,0.f,0.f,0.f};
    #pragma unroll
    for (int j = 0; j < 16; j++) {
        float4 A = __ldg(row + 2*j);
        float4 B = __ldg(row + 2*j + 1);
        RED_ACC(a0, a1, A.x, A.y, A.z, A.w, B.x, B.y, B.z, B.w);
        dst[4*j+0] = bf16pack(A.x, A.y);
        dst[4*j+1] = bf16pack(A.z, A.w);
        dst[4*j+2] = bf16pack(B.x, B.y);
        dst[4*j+3] = bf16pack(B.z, B.w);
    }
    dst[64] = dst[65] = dst[66] = dst[67] = 0u;
    float c2 = red_combine(a0, a1);
    g_cn[gw] = c2;
    atomicMax(&g_cmax[gw >> 10], __float_as_uint(c2));   // c2 > 0
}

// ---------------------------------------------------------------------------
// Main kernel: bf16 HMMA filter (ldmatrix B frags from cp.async double-
// buffered smem, 2 CTAs/SM, split accumulator chains for 2x tensor ILP)
// + validated exact rescore / update / r2 / loss.
// ---------------------------------------------------------------------------
__global__ __launch_bounds__(NT, 2)
void rvq_kernel(const float* __restrict__ x,
                const float* __restrict__ cb,
                float* __restrict__ out, int write_loss)
{
    extern __shared__ char sm[];
    unsigned long long* bestkey = (unsigned long long*)(sm + SM_BEST);
    double*   red  = (double*)(sm + SM_RED);
    float*    r2_s = (float*)(sm + SM_R2);
    float*    smin = (float*)(sm + SM_SMIN);
    float*    c2s  = (float*)(sm + SM_C2);
    int*      cnts = (int*)(sm + SM_CNT);
    float*    rs   = (float*)(sm + SM_RS);
    float4*   rs4  = (float4*)rs;
    const unsigned csb = smem_u32(sm + SM_CS);
    const unsigned c2b = smem_u32(sm + SM_C2);

    const int tid  = threadIdx.x;
    const int lane = tid & 31;
    const int g    = lane >> 2;       // mma group id (0..7)
    const int tig  = lane & 3;        // thread in group
    const int tw   = (tid >> 5) * 16; // warp token base
    const int lm_r = lane & 7;        // ldmatrix row
    const int lm_m = lane >> 3;       // ldmatrix matrix id

    const int blk = blockIdx.x;
    const int b   = blk >> 4;
    const int t0  = (blk & 15) * TM;
    const float* xb = x + (size_t)b * DD * TT + t0;
    unsigned long long* candg = g_cand + (size_t)blk * CAP;

    // Load initial residual r0 = x (transposed [d][token])
    for (int i = tid; i < DD*TM/4; i += NT) {
        int tok4 = i & 31, d = i >> 5;
        float4 v = __ldg((const float4*)(xb + (size_t)d * TT) + tok4);
        rs4[d * (TM/4) + tok4] = v;
    }
    __syncthreads();

    // Initial r2 (validated association)
    if (tid < TM) {
        float a0[4] = {0.f,0.f,0.f,0.f}, a1[4] = {0.f,0.f,0.f,0.f};
        #pragma unroll
        for (int j = 0; j < 16; j++) {
            int d = 8*j;
            RED_ACC(a0, a1,
                    rs[(d+0)*TM + tid], rs[(d+1)*TM + tid],
                    rs[(d+2)*TM + tid], rs[(d+3)*TM + tid],
                    rs[(d+4)*TM + tid], rs[(d+5)*TM + tid],
                    rs[(d+6)*TM + tid], rs[(d+7)*TM + tid]);
        }
        r2_s[tid] = red_combine(a0, a1);
    }
    __syncthreads();

    double lossAcc = 0.0;

    for (int q = 0; q < QQ; q++) {
        if (tid < TM) bestkey[tid] = 0xFFFFFFFFFFFFFFFFull;
        if (tid == 0) cnts[0] = 0;

        const float* cnq = g_cn + q * KK;

        // Build A fragments straight from rs (per warp; tokens tlo/thi)
        const int tlo = tw + g, thi = tw + 8 + g;
        unsigned af[8][4];
        #pragma unroll
        for (int kt = 0; kt < 8; kt++) {
            int d0 = kt*16 + 2*tig;
            af[kt][0] = bf16pack(rs[(d0  )*TM + tlo], rs[(d0+1)*TM + tlo]);
            af[kt][1] = bf16pack(rs[(d0  )*TM + thi], rs[(d0+1)*TM + thi]);
            af[kt][2] = bf16pack(rs[(d0+8)*TM + tlo], rs[(d0+9)*TM + tlo]);
            af[kt][3] = bf16pack(rs[(d0+8)*TM + thi], rs[(d0+9)*TM + thi]);
        }

        const float cmax = __uint_as_float(g_cmax[q]);
        const float wlo = __fmaf_rn(0.05f, sqrtf(r2_s[tlo] * cmax), 1.0f);
        const float whi = __fmaf_rn(0.05f, sqrtf(r2_s[thi] * cmax), 1.0f);
        float mlo = 3.4e38f, mhi = 3.4e38f;

        // Prefetch chunk 0 into buffer 0 (async)
        {
            const char* src = (const char*)(g_cb16 + (size_t)(q*KK) * KPW);
            for (int i = tid; i < CHB/16; i += NT)
                CP_ASYNC16(csb + (unsigned)(i*16), src + i*16);
            if (tid < 16)
                CP_ASYNC16(c2b + (unsigned)(tid*16), (const char*)cnq + tid*16);
            CP_COMMIT();
        }

        for (int ch = 0; ch < NCH; ch++) {
            const int buf = ch & 1;
            __syncthreads();   // prev compute on buf^1 done before overwrite
            if (ch < NCH - 1) {
                const int nb = buf ^ 1;
                const char* src =
                    (const char*)(g_cb16 + (size_t)(q*KK + (ch+1)*KC) * KPW);
                for (int i = tid; i < CHB/16; i += NT)
                    CP_ASYNC16(csb + (unsigned)(nb*CHB + i*16), src + i*16);
                if (tid < 16)
                    CP_ASYNC16(c2b + (unsigned)(nb*256 + tid*16),
                               (const char*)(cnq + (ch+1)*KC) + tid*16);
                CP_COMMIT();
                CP_WAIT1();
            } else {
                CP_WAIT0();
            }
            __syncthreads();

            #pragma unroll 2
            for (int nt = 0; nt < 8; nt++) {   // 8 groups per 64-code chunk
                unsigned bf[16];
                unsigned rowb = csb + (unsigned)(buf*CHB)
                              + (unsigned)((nt*8 + lm_r) * (KPW*4) + lm_m*16);
                ldm4(bf + 0,  rowb);
                ldm4(bf + 4,  rowb + 64);
                ldm4(bf + 8,  rowb + 128);
                ldm4(bf + 12, rowb + 192);

                // Two independent accumulator chains (kt 0-3 and kt 4-7):
                // halves the dependent-MMA chain, doubling tensor ILP.
                float c0a = 0.f, c1a = 0.f, c2a = 0.f, c3a = 0.f;
                float c0b = 0.f, c1b = 0.f, c2b2 = 0.f, c3b = 0.f;
                #pragma unroll
                for (int kt = 0; kt < 4; kt++) {
                    mma_bf16(c0a, c1a, c2a, c3a,
                             af[kt][0], af[kt][1], af[kt][2], af[kt][3],
                             bf[2*kt], bf[2*kt+1]);
                    mma_bf16(c0b, c1b, c2b2, c3b,
                             af[kt+4][0], af[kt+4][1], af[kt+4][2], af[kt+4][3],
                             bf[2*kt+8], bf[2*kt+9]);
                }
                float c0 = c0a + c0b, c1 = c1a + c1b;
                float c2v = c2a + c2b2, c3 = c3a + c3b;

                float cc0 = c2s[buf*KC + nt*8 + 2*tig];
                float cc1 = c2s[buf*KC + nt*8 + 2*tig + 1];
                float s0 = cc0 - 2.f*c0,  s1 = cc1 - 2.f*c1;   // token tlo
                float s2 = cc0 - 2.f*c2v, s3 = cc1 - 2.f*c3;   // token thi
                mlo = fminf(mlo, fminf(s0, s1));
                mhi = fminf(mhi, fminf(s2, s3));
                mlo = fminf(mlo, __shfl_xor_sync(0xffffffffu, mlo, 1));
                mlo = fminf(mlo, __shfl_xor_sync(0xffffffffu, mlo, 2));
                mhi = fminf(mhi, __shfl_xor_sync(0xffffffffu, mhi, 1));
                mhi = fminf(mhi, __shfl_xor_sync(0xffffffffu, mhi, 2));
                int code0 = ch*KC + nt*8 + 2*tig;
                float tl = mlo + wlo, th = mhi + whi;
                if (s0 <= tl || s1 <= tl || s2 <= th || s3 <= th) {
                    if (s0 <= tl) { int p = atomicAdd(cnts, 1); if (p < CAP)
                        candg[p] = ((unsigned long long)__float_as_uint(s0) << 32)
                                 | (unsigned)((tlo << 10) | code0); }
                    if (s1 <= tl) { int p = atomicAdd(cnts, 1); if (p < CAP)
                        candg[p] = ((unsigned long long)__float_as_uint(s1) << 32)
                                 | (unsigned)((tlo << 10) | (code0 + 1)); }
                    if (s2 <= th) { int p = atomicAdd(cnts, 1); if (p < CAP)
                        candg[p] = ((unsigned long long)__float_as_uint(s2) << 32)
                                 | (unsigned)((thi << 10) | code0); }
                    if (s3 <= th) { int p = atomicAdd(cnts, 1); if (p < CAP)
                        candg[p] = ((unsigned long long)__float_as_uint(s3) << 32)
                                 | (unsigned)((thi << 10) | (code0 + 1)); }
                }
            }
        }
        // Final per-token approx minima (tig 0 holds quad-merged value)
        if (tig == 0) { smin[tlo] = mlo; smin[thi] = mhi; }
        __syncthreads();

        int cnt = cnts[0];
        if (cnt <= CAP) {
            // Exact rescore of survivors (validated chain)
            for (int i = tid; i < cnt; i += NT) {
                unsigned long long e = candg[i];
                float sv = __uint_as_float((unsigned)(e >> 32));
                unsigned tc = (unsigned)e;
                int tok = (tc >> 10) & 127, k = tc & 1023;
                float Wk = __fmaf_rn(0.05f, sqrtf(r2_s[tok] * cmax), 1.0f);
                if (sv <= smin[tok] + Wk) {
                    unsigned long long key =
                        exact_key(rs, cb, cnq, r2_s[tok], q, tok, k);
                    atomicMin(&bestkey[tok], key);
                }
            }
        } else {
            // overflow fallback: exact full scan (deterministic, ~never)
            if (tid < TM) {
                unsigned long long bk = 0xFFFFFFFFFFFFFFFFull;
                for (int k = 0; k < KK; k++) {
                    unsigned long long key =
                        exact_key(rs, cb, cnq, r2_s[tid], q, tid, k);
                    if (key < bk) bk = key;
                }
                bestkey[tid] = bk;
            }
        }
        __syncthreads();

        // Residual update + next r2 (validated path, UNCHANGED)
        if (tid < TM) {
            const int tok = tid;
            const int widx = (int)(bestkey[tok] & 0xFFFFFFFFull);
            const float4* crow =
                (const float4*)(cb + ((size_t)q * KK + widx) * DD);
            float a0[4] = {0.f,0.f,0.f,0.f}, a1[4] = {0.f,0.f,0.f,0.f};
            float lsum = 0.0f;
            #pragma unroll
            for (int j = 0; j < 16; j++) {
                float4 cA = __ldg(crow + 2*j);
                float4 cB = __ldg(crow + 2*j + 1);
                int d = 8*j;
                float n0 = __fsub_rn(rs[(d+0)*TM + tok], cA.x);
                float n1 = __fsub_rn(rs[(d+1)*TM + tok], cA.y);
                float n2 = __fsub_rn(rs[(d+2)*TM + tok], cA.z);
                float n3 = __fsub_rn(rs[(d+3)*TM + tok], cA.w);
                float n4 = __fsub_rn(rs[(d+4)*TM + tok], cB.x);
                float n5 = __fsub_rn(rs[(d+5)*TM + tok], cB.y);
                float n6 = __fsub_rn(rs[(d+6)*TM + tok], cB.z);
                float n7 = __fsub_rn(rs[(d+7)*TM + tok], cB.w);
                rs[(d+0)*TM + tok] = n0;
                rs[(d+1)*TM + tok] = n1;
                rs[(d+2)*TM + tok] = n2;
                rs[(d+3)*TM + tok] = n3;
                rs[(d+4)*TM + tok] = n4;
                rs[(d+5)*TM + tok] = n5;
                rs[(d+6)*TM + tok] = n6;
                rs[(d+7)*TM + tok] = n7;
                RED_ACC(a0, a1, n0, n1, n2, n3, n4, n5, n6, n7);
                lsum += n0*n0 + n1*n1 + n2*n2 + n3*n3
                      + n4*n4 + n5*n5 + n6*n6 + n7*n7;
            }
            r2_s[tok] = red_combine(a0, a1);
            lossAcc += (double)lsum;
        }
        __syncthreads();   // rs/r2 visible before next stage's A-frag build
    }

    // quantized = x - r_final (telescoped), layout [B,D,T]
    for (int i = tid; i < DD*TM/4; i += NT) {
        int tok4 = i & 31, d = i >> 5;
        float4 xv = __ldg((const float4*)(xb + (size_t)d * TT) + tok4);
        float4 rv = rs4[d * (TM/4) + tok4];
        float4 o;
        o.x = xv.x - rv.x; o.y = xv.y - rv.y;
        o.z = xv.z - rv.z; o.w = xv.w - rv.w;
        ((float4*)(out + ((size_t)b * DD + d) * TT + t0))[tok4] = o;
    }

    // total_loss = sum_q mean(r_{q+1}^2)
    if (write_loss) {
        #pragma unroll
        for (int off = 16; off > 0; off >>= 1)
            lossAcc += __shfl_xor_sync(0xffffffffu, lossAcc, off);
        if ((tid & 31) == 0) red[tid >> 5] = lossAcc;
        __syncthreads();
        if (tid == 0) {
            double s = 0.0;
            #pragma unroll
            for (int w = 0; w < 8; w++) s += red[w];
            atomicAdd(out + OUT_ELEMS, (float)(s * (1.0 / (double)OUT_ELEMS)));
        }
    }
}

// ---------------------------------------------------------------------------
extern "C" void kernel_launch(void* const* d_in, const int* in_sizes, int n_in,
                              void* d_out, int out_size)
{
    const float* x  = (const float*)d_in[0];   // [16,128,2048] fp32
    const float* cb = (const float*)d_in[1];   // [30,1024,128] fp32
    float* out = (float*)d_out;                // [16,128,2048] + loss scalar
    int write_loss = (out_size > OUT_ELEMS) ? 1 : 0;

    rvq_prep0_kernel<<<1, 64>>>(out, write_loss);
    rvq_norm_kernel<<<(QQ*KK + 255)/256, 256>>>(cb);

    cudaFuncSetAttribute(rvq_kernel,
                         cudaFuncAttributeMaxDynamicSharedMemorySize, SM_TOTAL);
    rvq_kernel<<<NBLK, NT, SM_TOTAL>>>(x, cb, out, write_loss);
}